// round 12
// baseline (speedup 1.0000x reference)
#include <cuda_runtime.h>
#include <cuda_fp16.h>
#include <math.h>
#include <stdint.h>

// Problem constants
#define CIN   1536
#define COUT  3072
#define TT    16
#define HF    14
#define WF    14
#define NOUT  7
#define NCELL (NOUT * NOUT)        // 49
#define NCOLS (TT * NCELL)         // 784
#define NPAD  832                  // 13 * 64
#define PLANE (HF * WF)            // 196

// ---------------------------------------------------------------------------
// Device scratch
// ---------------------------------------------------------------------------
__device__ __align__(16) __half g_Wh[COUT * CIN];           // W fp16
__device__ __align__(16) __half g_Bh[CIN * NPAD];           // y fp16, k-major
__device__ __align__(16) float g_G[COUT * NCOLS];           // gelu(bn(conv))
__device__ __align__(16) float g_MR[COUT * NCOLS];          // roi means
__device__ __align__(16) float g_tapw[TT * NCELL * 16];
__device__ __align__(16) int   g_tapi[TT * NCELL * 16];
__device__ int   g_win[TT * 2];

// ---------------------------------------------------------------------------
// Kernel P: merged convert_w (2x float4/thread) + pack (2 elems/thread) + taps
// ---------------------------------------------------------------------------
#define W8CNT ((COUT * CIN) / 8)
#define W8BLK ((W8CNT + 255) / 256)
#define PK2CNT ((CIN * NPAD) / 2)
#define PK2BLK ((PK2CNT + 255) / 256)

__global__ void prep_kernel(const float* __restrict__ W, const float* __restrict__ y,
                            const float* __restrict__ rois) {
    if (blockIdx.x < W8BLK) {
        int i = blockIdx.x * 256 + threadIdx.x;
        if (i >= W8CNT) return;
        float4 v0 = ((const float4*)W)[i * 2 + 0];
        float4 v1 = ((const float4*)W)[i * 2 + 1];
        __half2* Wh2 = (__half2*)g_Wh;
        Wh2[i * 4 + 0] = __half2{__float2half_rn(v0.x), __float2half_rn(v0.y)};
        Wh2[i * 4 + 1] = __half2{__float2half_rn(v0.z), __float2half_rn(v0.w)};
        Wh2[i * 4 + 2] = __half2{__float2half_rn(v1.x), __float2half_rn(v1.y)};
        Wh2[i * 4 + 3] = __half2{__float2half_rn(v1.z), __float2half_rn(v1.w)};
    } else if (blockIdx.x < W8BLK + PK2BLK) {
        int i2 = (blockIdx.x - W8BLK) * 256 + threadIdx.x;
        if (i2 >= PK2CNT) return;
        int idx = i2 * 2;
        int k = idx / NPAD;
        int n0 = idx - k * NPAD;
        float v[2] = {0.0f, 0.0f};
#pragma unroll
        for (int j = 0; j < 2; j++) {
            int n = n0 + j;
            if (n < NCOLS) {
                int t = n / NCELL;
                int r = n - t * NCELL;
                int oy = r / NOUT;
                int ox = r - oy * NOUT;
                v[j] = y[((k * TT + t) * HF + 2 * oy) * WF + 2 * ox];
            }
        }
        ((__half2*)g_Bh)[i2] = __half2{__float2half_rn(v[0]), __float2half_rn(v[1])};
    } else {
        const int t = blockIdx.x - (W8BLK + PK2BLK);
        const int cell = threadIdx.x;
        if (cell >= NCELL) return;
        const float SC = 1.0f / 16.0f;
        float bx1 = rois[t * 4 + 0] * SC;
        float by1 = rois[t * 4 + 1] * SC;
        float bx2 = rois[t * 4 + 2] * SC;
        float by2 = rois[t * 4 + 3] * SC;
        float bw = fmaxf(bx2 - bx1, 1.0f) / (float)NOUT;
        float bh = fmaxf(by2 - by1, 1.0f) / (float)NOUT;

        if (cell == 0) {
            int sxi = (int)floorf(bx1);
            int syi = (int)floorf(by1);
            int exi = (int)ceilf(bx2);
            int eyi = (int)ceilf(by2);
            g_win[t * 2 + 0] = (syi + NOUT < HF) ? syi : (eyi - NOUT);
            g_win[t * 2 + 1] = (sxi + NOUT < HF) ? sxi : (exi - NOUT);
        }

        int oy = cell / NOUT;
        int ox = cell - oy * NOUT;
        float* tw = g_tapw + (t * NCELL + cell) * 16;
        int*   ti = g_tapi + (t * NCELL + cell) * 16;

#pragma unroll
        for (int s = 0; s < 2; s++) {
#pragma unroll
            for (int r = 0; r < 2; r++) {
                int base = (s * 2 + r) * 4;
                float py = by1 + ((float)oy + ((float)s + 0.5f) * 0.5f) * bh;
                float px = bx1 + ((float)ox + ((float)r + 0.5f) * 0.5f) * bw;
                bool oob = (py < -1.0f) | (py > (float)HF) | (px < -1.0f) | (px > (float)WF);
                if (oob) {
                    tw[base + 0] = 0.f; tw[base + 1] = 0.f; tw[base + 2] = 0.f; tw[base + 3] = 0.f;
                    ti[base + 0] = 0;   ti[base + 1] = 0;   ti[base + 2] = 0;   ti[base + 3] = 0;
                } else {
                    float yc = fminf(fmaxf(py, 0.0f), (float)(HF - 1));
                    float xc = fminf(fmaxf(px, 0.0f), (float)(WF - 1));
                    int y0 = (int)floorf(yc);
                    int x0 = (int)floorf(xc);
                    int y1i = min(y0 + 1, HF - 1);
                    int x1i = min(x0 + 1, WF - 1);
                    float ly = yc - (float)y0;
                    float lx = xc - (float)x0;
                    tw[base + 0] = 0.25f * (1.f - ly) * (1.f - lx);
                    tw[base + 1] = 0.25f * (1.f - ly) * lx;
                    tw[base + 2] = 0.25f * ly * (1.f - lx);
                    tw[base + 3] = 0.25f * ly * lx;
                    ti[base + 0] = y0 * WF + x0;
                    ti[base + 1] = y0 * WF + x1i;
                    ti[base + 2] = y1i * WF + x0;
                    ti[base + 3] = y1i * WF + x1i;
                }
            }
        }
    }
}

// ---------------------------------------------------------------------------
// Kernel MR (side stream): ROI means -> g_MR. Overlaps with GEMM.
// 32 channels/block, 256 threads, grid (COUT/32, TT). Static smem ~33KB.
// ---------------------------------------------------------------------------
#define CH 32
#define TSTR 197

__global__ void __launch_bounds__(256) mr_kernel(const float* __restrict__ x_t) {
    __shared__ __align__(16) float s_tw[NCELL * 16];
    __shared__ __align__(16) int   s_ti[NCELL * 16];
    __shared__ float ts[CH * TSTR];

    const int t = blockIdx.y;
    const int c0 = blockIdx.x * CH;
    const int tid = threadIdx.x;

    {
        const float4* gw4 = (const float4*)(g_tapw + t * NCELL * 16);
        const int4*   gi4 = (const int4*)(g_tapi + t * NCELL * 16);
        for (int i = tid; i < NCELL * 4; i += 256) {
            ((float4*)s_tw)[i] = gw4[i];
            ((int4*)s_ti)[i] = gi4[i];
        }
    }
    const float4* src4 = (const float4*)x_t;
    for (int i = tid; i < CH * 49; i += 256) {
        int c = i / 49, q = i - (i / 49) * 49;
        float4 v = src4[(size_t)((c0 + c) * TT + t) * 49 + q];
        float* dst = ts + c * TSTR + q * 4;
        dst[0] = v.x; dst[1] = v.y; dst[2] = v.z; dst[3] = v.w;
    }
    __syncthreads();

    // warp = one cell across 32 channels; stride 197 coprime 32 -> conflict-free
    for (int j = tid; j < NCELL * 32; j += 256) {
        int cell = j >> 5;
        int p = j & 31;
        const float* tp = ts + p * TSTR;
        const float4* tw4 = (const float4*)(s_tw + cell * 16);
        const int4*   ti4 = (const int4*)(s_ti + cell * 16);
        float mr = 0.0f;
#pragma unroll
        for (int g4 = 0; g4 < 4; g4++) {
            float4 w = tw4[g4];
            int4 ix = ti4[g4];
            mr = fmaf(w.x, tp[ix.x], mr);
            mr = fmaf(w.y, tp[ix.y], mr);
            mr = fmaf(w.z, tp[ix.z], mr);
            mr = fmaf(w.w, tp[ix.w], mr);
        }
        g_MR[(size_t)(c0 + p) * NCOLS + t * NCELL + cell] = mr;
    }
}

// ---------------------------------------------------------------------------
// Kernel 2: fp16 tensor-core GEMM + bias + BN + exact GELU (R8 config)
// BM=64, BN=64, BK=32; 128 threads; 4-stage cp.async depth-3
// ---------------------------------------------------------------------------
#define BM 64
#define BN 64
#define BK 32
#define KSTEPS (CIN / BK)     // 48
#define ASTR 40
#define BSTR 72

#define AH_OFF 0
#define BH_OFF (BM * ASTR)                  // 2560
#define STAGE_ELEMS (BH_OFF + BK * BSTR)    // 4864 halfs = 9728B
#define NSTAGE 4
#define SMEM_BYTES (NSTAGE * STAGE_ELEMS * 2)  // 38912

__device__ __forceinline__ void cp16(void* smem, const void* gmem) {
    unsigned sa = (unsigned)__cvta_generic_to_shared(smem);
    asm volatile("cp.async.cg.shared.global [%0], [%1], 16;\n" :: "r"(sa), "l"(gmem));
}
__device__ __forceinline__ void ldsm4(unsigned* r, const void* p) {
    unsigned a = (unsigned)__cvta_generic_to_shared(p);
    asm volatile("ldmatrix.sync.aligned.m8n8.x4.shared.b16 {%0,%1,%2,%3}, [%4];\n"
        : "=r"(r[0]), "=r"(r[1]), "=r"(r[2]), "=r"(r[3]) : "r"(a));
}
__device__ __forceinline__ void ldsm4t(unsigned* r, const void* p) {
    unsigned a = (unsigned)__cvta_generic_to_shared(p);
    asm volatile("ldmatrix.sync.aligned.m8n8.x4.trans.shared.b16 {%0,%1,%2,%3}, [%4];\n"
        : "=r"(r[0]), "=r"(r[1]), "=r"(r[2]), "=r"(r[3]) : "r"(a));
}

#define MMA_F16(c, a, b0, b1)                                               \
    asm volatile(                                                           \
        "mma.sync.aligned.m16n8k16.row.col.f32.f16.f16.f32 "                \
        "{%0,%1,%2,%3}, {%4,%5,%6,%7}, {%8,%9}, {%0,%1,%2,%3};\n"           \
        : "+f"(c[0]), "+f"(c[1]), "+f"(c[2]), "+f"(c[3])                    \
        : "r"(a[0]), "r"(a[1]), "r"(a[2]), "r"(a[3]), "r"(b0), "r"(b1))

extern __shared__ __half smem_buf[];

__global__ void __launch_bounds__(128) gemm_bn_gelu_kernel(
    const float* __restrict__ bias,
    const float* __restrict__ gamma,
    const float* __restrict__ beta,
    const float* __restrict__ rmean,
    const float* __restrict__ rvar)
{
    const int tid = threadIdx.x;
    const int bm = blockIdx.y * BM;
    const int bn = blockIdx.x * BN;

    const int lane = tid & 31;
    const int warp = tid >> 5;
    const int wm = warp >> 1;
    const int wn = warp & 1;
    const int frow = lane >> 2;
    const int fcolp = (lane & 3) * 2;
    const int sel = lane >> 3;
    const int lr = lane & 7;

    float acc[2][4][4];
#pragma unroll
    for (int mt = 0; mt < 2; mt++)
#pragma unroll
        for (int nt = 0; nt < 4; nt++)
#pragma unroll
            for (int i = 0; i < 4; i++) acc[mt][nt][i] = 0.0f;

    auto prefetch = [&](int s, int k0) {
        __half* st = smem_buf + s * STAGE_ELEMS;
#pragma unroll
        for (int c = tid; c < 256; c += 128) {
            int row = c >> 2;
            int u = c & 3;
            cp16(&st[AH_OFF + row * ASTR + u * 8],
                 &g_Wh[(size_t)(bm + row) * CIN + k0 + u * 8]);
        }
#pragma unroll
        for (int c = tid; c < 256; c += 128) {
            int row = c >> 3;
            int u = c & 7;
            cp16(&st[BH_OFF + row * BSTR + u * 8],
                 &g_Bh[(size_t)(k0 + row) * NPAD + bn + u * 8]);
        }
        asm volatile("cp.async.commit_group;\n");
    };

    auto consume = [&](int s) {
        const __half* st = smem_buf + s * STAGE_ELEMS;
        const unsigned short* sAh = (const unsigned short*)(st + AH_OFF);
        const unsigned short* sBh = (const unsigned short*)(st + BH_OFF);
#pragma unroll
        for (int h = 0; h < 2; h++) {
            const int kb = h * 16;
            unsigned ah[2][4], bh[2][4];
            const int arow = (sel & 1) * 8 + lr;
            const int akof = (sel >> 1) * 8;
#pragma unroll
            for (int mt = 0; mt < 2; mt++) {
                int r = wm * 32 + mt * 16 + arow;
                ldsm4(ah[mt], &sAh[r * ASTR + kb + akof]);
            }
#pragma unroll
            for (int np = 0; np < 2; np++) {
                int kr = kb + (sel & 1) * 8 + lr;
                int nc = wn * 32 + np * 16 + (sel >> 1) * 8;
                ldsm4t(bh[np], &sBh[kr * BSTR + nc]);
            }
#pragma unroll
            for (int np = 0; np < 2; np++)
#pragma unroll
                for (int q = 0; q < 2; q++) {
                    int nt = np * 2 + q;
#pragma unroll
                    for (int mt = 0; mt < 2; mt++)
                        MMA_F16(acc[mt][nt], ah[mt], bh[np][q * 2], bh[np][q * 2 + 1]);
                }
        }
    };

    prefetch(0, 0);
    prefetch(1, BK);
    prefetch(2, 2 * BK);

    for (int ks = 0; ks < KSTEPS; ks++) {
        int rem = KSTEPS - 1 - ks;
        if (rem >= 2)      asm volatile("cp.async.wait_group 2;\n");
        else if (rem == 1) asm volatile("cp.async.wait_group 1;\n");
        else               asm volatile("cp.async.wait_group 0;\n");
        __syncthreads();
        if (ks + 3 < KSTEPS) prefetch((ks + 3) & 3, (ks + 3) * BK);
        consume(ks & 3);
    }

    // Epilogue: bias + BN + exact GELU -> g_G
#pragma unroll
    for (int mt = 0; mt < 2; mt++) {
        int r0g = bm + wm * 32 + mt * 16 + frow;
#pragma unroll
        for (int half = 0; half < 2; half++) {
            int o = r0g + half * 8;
            float inv = gamma[o] * rsqrtf(rvar[o] + 1e-6f);
            float b0 = bias[o];
            float mu = rmean[o];
            float be = beta[o];
#pragma unroll
            for (int nt = 0; nt < 4; nt++) {
                int n = bn + wn * 32 + nt * 8 + fcolp;
                if (n < NCOLS) {
                    float v0 = acc[mt][nt][half * 2 + 0] + b0;
                    float v1 = acc[mt][nt][half * 2 + 1] + b0;
                    v0 = (v0 - mu) * inv + be;
                    v1 = (v1 - mu) * inv + be;
                    v0 = v0 * normcdff(v0);
                    v1 = v1 * normcdff(v1);
                    *(float2*)&g_G[(size_t)o * NCOLS + n] = make_float2(v0, v1);
                }
            }
        }
    }
}

// ---------------------------------------------------------------------------
// Kernel F: final streaming residual + placement (no gather)
// out = x_t + mask * (g_G * g_MR). 32 channels/block, 256 threads.
// ---------------------------------------------------------------------------
__global__ void __launch_bounds__(256) final_kernel(
    const float* __restrict__ x_t,
    float* __restrict__ out)
{
    __shared__ float wsm[CH * NCELL];
    __shared__ int s_mask[PLANE];

    const int t = blockIdx.y;
    const int c0 = blockIdx.x * CH;
    const int tid = threadIdx.x;

    if (tid < PLANE) {
        const int mt = g_win[t * 2 + 0];
        const int ml = g_win[t * 2 + 1];
        int h = tid / WF;
        int w = tid - h * WF;
        int oy = h - mt, ox = w - ml;
        s_mask[tid] = (oy >= 0 && oy < NOUT && ox >= 0 && ox < NOUT) ? oy * NOUT + ox : -1;
    }
    for (int i = tid; i < CH * NCELL; i += 256) {
        int p = i / NCELL, cell = i - (i / NCELL) * NCELL;
        size_t g = (size_t)(c0 + p) * NCOLS + t * NCELL + cell;
        wsm[i] = g_G[g] * g_MR[g];
    }
    __syncthreads();

    const float4* src4 = (const float4*)x_t;
    float4* dst4 = (float4*)out;
    for (int i = tid; i < CH * 49; i += 256) {
        int c = i / 49, q = i - (i / 49) * 49;
        size_t off = (size_t)((c0 + c) * TT + t) * 49 + q;
        float4 v = src4[off];
        float* vp = (float*)&v;
        int e0 = q * 4;
#pragma unroll
        for (int j = 0; j < 4; j++) {
            int mi = s_mask[e0 + j];
            if (mi >= 0) vp[j] += wsm[c * NCELL + mi];
        }
        dst4[off] = v;
    }
}

// ---------------------------------------------------------------------------
// Launch: prep -> fork{ GEMM (stream 0) || mr (side stream) } -> join -> final
// ---------------------------------------------------------------------------
extern "C" void kernel_launch(void* const* d_in, const int* in_sizes, int n_in,
                              void* d_out, int out_size) {
    const float* y      = (const float*)d_in[0];
    const float* x_t    = (const float*)d_in[1];
    const float* rois   = (const float*)d_in[2];
    const float* conv_w = (const float*)d_in[3];
    const float* conv_b = (const float*)d_in[4];
    const float* gamma  = (const float*)d_in[5];
    const float* beta   = (const float*)d_in[6];
    const float* rmean  = (const float*)d_in[7];
    const float* rvar   = (const float*)d_in[8];
    float* out = (float*)d_out;

    // Host-side resources created once (no device memory involved).
    static cudaStream_t s_side = nullptr;
    static cudaEvent_t s_evFork = nullptr, s_evJoin = nullptr;
    if (s_side == nullptr) {
        cudaStreamCreateWithFlags(&s_side, cudaStreamNonBlocking);
        cudaEventCreateWithFlags(&s_evFork, cudaEventDisableTiming);
        cudaEventCreateWithFlags(&s_evJoin, cudaEventDisableTiming);
        cudaFuncSetAttribute(gemm_bn_gelu_kernel,
                             cudaFuncAttributeMaxDynamicSharedMemorySize, SMEM_BYTES);
    }

    prep_kernel<<<W8BLK + PK2BLK + TT, 256>>>(conv_w, y, rois);

    // Fork: mr on side stream, GEMM on default stream (concurrent).
    cudaEventRecord(s_evFork, 0);
    cudaStreamWaitEvent(s_side, s_evFork, 0);
    {
        dim3 grid(COUT / CH, TT);
        mr_kernel<<<grid, 256, 0, s_side>>>(x_t);
    }
    cudaEventRecord(s_evJoin, s_side);
    {
        dim3 grid(NPAD / BN, COUT / BM);  // (13, 48)
        gemm_bn_gelu_kernel<<<grid, 128, SMEM_BYTES>>>(conv_b, gamma, beta, rmean, rvar);
    }
    // Join: default stream waits for mr before final.
    cudaStreamWaitEvent(0, s_evJoin, 0);
    {
        dim3 grid(COUT / CH, TT);
        final_kernel<<<grid, 256>>>(x_t, out);
    }
}

// round 13
// speedup vs baseline: 1.5357x; 1.5357x over previous
#include <cuda_runtime.h>
#include <cuda_fp16.h>
#include <math.h>
#include <stdint.h>

// Problem constants
#define CIN   1536
#define COUT  3072
#define TT    16
#define HF    14
#define WF    14
#define NOUT  7
#define NCELL (NOUT * NOUT)        // 49
#define NCOLS (TT * NCELL)         // 784
#define NPAD  832                  // 13 * 64
#define PLANE (HF * WF)            // 196

// ---------------------------------------------------------------------------
// Device scratch
// ---------------------------------------------------------------------------
__device__ __align__(16) __half g_Wh[COUT * CIN];           // W fp16
__device__ __align__(16) __half g_Bh[CIN * NPAD];           // y fp16, k-major
__device__ __align__(16) float g_G[COUT * NCOLS];           // gelu(bn(conv))
__device__ __align__(16) float g_tapw[TT * NCELL * 16];
__device__ __align__(16) int   g_tapi[TT * NCELL * 16];
__device__ int   g_win[TT * 2];

// ---------------------------------------------------------------------------
// Kernel P: merged convert_w (2x float4/thread) + pack (2 elems/thread) + taps
// (R11 version, measured 10.2us)
// ---------------------------------------------------------------------------
#define W8CNT ((COUT * CIN) / 8)
#define W8BLK ((W8CNT + 255) / 256)
#define PK2CNT ((CIN * NPAD) / 2)
#define PK2BLK ((PK2CNT + 255) / 256)

__global__ void prep_kernel(const float* __restrict__ W, const float* __restrict__ y,
                            const float* __restrict__ rois) {
    if (blockIdx.x < W8BLK) {
        int i = blockIdx.x * 256 + threadIdx.x;
        if (i >= W8CNT) return;
        float4 v0 = ((const float4*)W)[i * 2 + 0];
        float4 v1 = ((const float4*)W)[i * 2 + 1];
        __half2* Wh2 = (__half2*)g_Wh;
        Wh2[i * 4 + 0] = __half2{__float2half_rn(v0.x), __float2half_rn(v0.y)};
        Wh2[i * 4 + 1] = __half2{__float2half_rn(v0.z), __float2half_rn(v0.w)};
        Wh2[i * 4 + 2] = __half2{__float2half_rn(v1.x), __float2half_rn(v1.y)};
        Wh2[i * 4 + 3] = __half2{__float2half_rn(v1.z), __float2half_rn(v1.w)};
    } else if (blockIdx.x < W8BLK + PK2BLK) {
        int i2 = (blockIdx.x - W8BLK) * 256 + threadIdx.x;
        if (i2 >= PK2CNT) return;
        int idx = i2 * 2;
        int k = idx / NPAD;
        int n0 = idx - k * NPAD;
        float v[2] = {0.0f, 0.0f};
#pragma unroll
        for (int j = 0; j < 2; j++) {
            int n = n0 + j;
            if (n < NCOLS) {
                int t = n / NCELL;
                int r = n - t * NCELL;
                int oy = r / NOUT;
                int ox = r - oy * NOUT;
                v[j] = y[((k * TT + t) * HF + 2 * oy) * WF + 2 * ox];
            }
        }
        ((__half2*)g_Bh)[i2] = __half2{__float2half_rn(v[0]), __float2half_rn(v[1])};
    } else {
        const int t = blockIdx.x - (W8BLK + PK2BLK);
        const int cell = threadIdx.x;
        if (cell >= NCELL) return;
        const float SC = 1.0f / 16.0f;
        float bx1 = rois[t * 4 + 0] * SC;
        float by1 = rois[t * 4 + 1] * SC;
        float bx2 = rois[t * 4 + 2] * SC;
        float by2 = rois[t * 4 + 3] * SC;
        float bw = fmaxf(bx2 - bx1, 1.0f) / (float)NOUT;
        float bh = fmaxf(by2 - by1, 1.0f) / (float)NOUT;

        if (cell == 0) {
            int sxi = (int)floorf(bx1);
            int syi = (int)floorf(by1);
            int exi = (int)ceilf(bx2);
            int eyi = (int)ceilf(by2);
            g_win[t * 2 + 0] = (syi + NOUT < HF) ? syi : (eyi - NOUT);
            g_win[t * 2 + 1] = (sxi + NOUT < HF) ? sxi : (exi - NOUT);
        }

        int oy = cell / NOUT;
        int ox = cell - oy * NOUT;
        float* tw = g_tapw + (t * NCELL + cell) * 16;
        int*   ti = g_tapi + (t * NCELL + cell) * 16;

#pragma unroll
        for (int s = 0; s < 2; s++) {
#pragma unroll
            for (int r = 0; r < 2; r++) {
                int base = (s * 2 + r) * 4;
                float py = by1 + ((float)oy + ((float)s + 0.5f) * 0.5f) * bh;
                float px = bx1 + ((float)ox + ((float)r + 0.5f) * 0.5f) * bw;
                bool oob = (py < -1.0f) | (py > (float)HF) | (px < -1.0f) | (px > (float)WF);
                if (oob) {
                    tw[base + 0] = 0.f; tw[base + 1] = 0.f; tw[base + 2] = 0.f; tw[base + 3] = 0.f;
                    ti[base + 0] = 0;   ti[base + 1] = 0;   ti[base + 2] = 0;   ti[base + 3] = 0;
                } else {
                    float yc = fminf(fmaxf(py, 0.0f), (float)(HF - 1));
                    float xc = fminf(fmaxf(px, 0.0f), (float)(WF - 1));
                    int y0 = (int)floorf(yc);
                    int x0 = (int)floorf(xc);
                    int y1i = min(y0 + 1, HF - 1);
                    int x1i = min(x0 + 1, WF - 1);
                    float ly = yc - (float)y0;
                    float lx = xc - (float)x0;
                    tw[base + 0] = 0.25f * (1.f - ly) * (1.f - lx);
                    tw[base + 1] = 0.25f * (1.f - ly) * lx;
                    tw[base + 2] = 0.25f * ly * (1.f - lx);
                    tw[base + 3] = 0.25f * ly * lx;
                    ti[base + 0] = y0 * WF + x0;
                    ti[base + 1] = y0 * WF + x1i;
                    ti[base + 2] = y1i * WF + x0;
                    ti[base + 3] = y1i * WF + x1i;
                }
            }
        }
    }
}

// ---------------------------------------------------------------------------
// Kernel 2: fp16 tensor-core GEMM + bias + BN + exact GELU (R8 config:
// BM=64, BN=64, BK=32; 128 threads; 4-stage cp.async depth-3)
// ---------------------------------------------------------------------------
#define BM 64
#define BN 64
#define BK 32
#define KSTEPS (CIN / BK)     // 48
#define ASTR 40
#define BSTR 72

#define AH_OFF 0
#define BH_OFF (BM * ASTR)                  // 2560
#define STAGE_ELEMS (BH_OFF + BK * BSTR)    // 4864 halfs = 9728B
#define NSTAGE 4
#define SMEM_BYTES (NSTAGE * STAGE_ELEMS * 2)  // 38912

__device__ __forceinline__ void cp16(void* smem, const void* gmem) {
    unsigned sa = (unsigned)__cvta_generic_to_shared(smem);
    asm volatile("cp.async.cg.shared.global [%0], [%1], 16;\n" :: "r"(sa), "l"(gmem));
}
__device__ __forceinline__ void ldsm4(unsigned* r, const void* p) {
    unsigned a = (unsigned)__cvta_generic_to_shared(p);
    asm volatile("ldmatrix.sync.aligned.m8n8.x4.shared.b16 {%0,%1,%2,%3}, [%4];\n"
        : "=r"(r[0]), "=r"(r[1]), "=r"(r[2]), "=r"(r[3]) : "r"(a));
}
__device__ __forceinline__ void ldsm4t(unsigned* r, const void* p) {
    unsigned a = (unsigned)__cvta_generic_to_shared(p);
    asm volatile("ldmatrix.sync.aligned.m8n8.x4.trans.shared.b16 {%0,%1,%2,%3}, [%4];\n"
        : "=r"(r[0]), "=r"(r[1]), "=r"(r[2]), "=r"(r[3]) : "r"(a));
}

#define MMA_F16(c, a, b0, b1)                                               \
    asm volatile(                                                           \
        "mma.sync.aligned.m16n8k16.row.col.f32.f16.f16.f32 "                \
        "{%0,%1,%2,%3}, {%4,%5,%6,%7}, {%8,%9}, {%0,%1,%2,%3};\n"           \
        : "+f"(c[0]), "+f"(c[1]), "+f"(c[2]), "+f"(c[3])                    \
        : "r"(a[0]), "r"(a[1]), "r"(a[2]), "r"(a[3]), "r"(b0), "r"(b1))

extern __shared__ __half smem_buf[];

__global__ void __launch_bounds__(128) gemm_bn_gelu_kernel(
    const float* __restrict__ bias,
    const float* __restrict__ gamma,
    const float* __restrict__ beta,
    const float* __restrict__ rmean,
    const float* __restrict__ rvar)
{
    const int tid = threadIdx.x;
    const int bm = blockIdx.y * BM;
    const int bn = blockIdx.x * BN;

    const int lane = tid & 31;
    const int warp = tid >> 5;
    const int wm = warp >> 1;
    const int wn = warp & 1;
    const int frow = lane >> 2;
    const int fcolp = (lane & 3) * 2;
    const int sel = lane >> 3;
    const int lr = lane & 7;

    float acc[2][4][4];
#pragma unroll
    for (int mt = 0; mt < 2; mt++)
#pragma unroll
        for (int nt = 0; nt < 4; nt++)
#pragma unroll
            for (int i = 0; i < 4; i++) acc[mt][nt][i] = 0.0f;

    auto prefetch = [&](int s, int k0) {
        __half* st = smem_buf + s * STAGE_ELEMS;
#pragma unroll
        for (int c = tid; c < 256; c += 128) {
            int row = c >> 2;
            int u = c & 3;
            cp16(&st[AH_OFF + row * ASTR + u * 8],
                 &g_Wh[(size_t)(bm + row) * CIN + k0 + u * 8]);
        }
#pragma unroll
        for (int c = tid; c < 256; c += 128) {
            int row = c >> 3;
            int u = c & 7;
            cp16(&st[BH_OFF + row * BSTR + u * 8],
                 &g_Bh[(size_t)(k0 + row) * NPAD + bn + u * 8]);
        }
        asm volatile("cp.async.commit_group;\n");
    };

    auto consume = [&](int s) {
        const __half* st = smem_buf + s * STAGE_ELEMS;
        const unsigned short* sAh = (const unsigned short*)(st + AH_OFF);
        const unsigned short* sBh = (const unsigned short*)(st + BH_OFF);
#pragma unroll
        for (int h = 0; h < 2; h++) {
            const int kb = h * 16;
            unsigned ah[2][4], bh[2][4];
            const int arow = (sel & 1) * 8 + lr;
            const int akof = (sel >> 1) * 8;
#pragma unroll
            for (int mt = 0; mt < 2; mt++) {
                int r = wm * 32 + mt * 16 + arow;
                ldsm4(ah[mt], &sAh[r * ASTR + kb + akof]);
            }
#pragma unroll
            for (int np = 0; np < 2; np++) {
                int kr = kb + (sel & 1) * 8 + lr;
                int nc = wn * 32 + np * 16 + (sel >> 1) * 8;
                ldsm4t(bh[np], &sBh[kr * BSTR + nc]);
            }
#pragma unroll
            for (int np = 0; np < 2; np++)
#pragma unroll
                for (int q = 0; q < 2; q++) {
                    int nt = np * 2 + q;
#pragma unroll
                    for (int mt = 0; mt < 2; mt++)
                        MMA_F16(acc[mt][nt], ah[mt], bh[np][q * 2], bh[np][q * 2 + 1]);
                }
        }
    };

    prefetch(0, 0);
    prefetch(1, BK);
    prefetch(2, 2 * BK);

    for (int ks = 0; ks < KSTEPS; ks++) {
        int rem = KSTEPS - 1 - ks;
        if (rem >= 2)      asm volatile("cp.async.wait_group 2;\n");
        else if (rem == 1) asm volatile("cp.async.wait_group 1;\n");
        else               asm volatile("cp.async.wait_group 0;\n");
        __syncthreads();
        if (ks + 3 < KSTEPS) prefetch((ks + 3) & 3, (ks + 3) * BK);
        consume(ks & 3);
    }

    // Epilogue: bias + BN + exact GELU -> g_G
#pragma unroll
    for (int mt = 0; mt < 2; mt++) {
        int r0g = bm + wm * 32 + mt * 16 + frow;
#pragma unroll
        for (int half = 0; half < 2; half++) {
            int o = r0g + half * 8;
            float inv = gamma[o] * rsqrtf(rvar[o] + 1e-6f);
            float b0 = bias[o];
            float mu = rmean[o];
            float be = beta[o];
#pragma unroll
            for (int nt = 0; nt < 4; nt++) {
                int n = bn + wn * 32 + nt * 8 + fcolp;
                if (n < NCOLS) {
                    float v0 = acc[mt][nt][half * 2 + 0] + b0;
                    float v1 = acc[mt][nt][half * 2 + 1] + b0;
                    v0 = (v0 - mu) * inv + be;
                    v1 = (v1 - mu) * inv + be;
                    v0 = v0 * normcdff(v0);
                    v1 = v1 * normcdff(v1);
                    *(float2*)&g_G[(size_t)o * NCOLS + n] = make_float2(v0, v1);
                }
            }
        }
    }
}

// ---------------------------------------------------------------------------
// Kernel 3: ROI-align + place + residual (v5: scatter-into-tile, branch-free
// store). 32 channels/block, 256 threads, grid (COUT/32, TT).
// ---------------------------------------------------------------------------
#define CH 32
#define TSTR 197

__global__ void __launch_bounds__(256) roi_place_kernel(
    const float* __restrict__ x_t,
    float* __restrict__ out)
{
    __shared__ __align__(16) float s_tw[NCELL * 16];
    __shared__ __align__(16) int   s_ti[NCELL * 16];
    __shared__ float ts[CH * TSTR];      // plane tiles, stride 197 (coprime 32)
    __shared__ float gsm[CH * NCELL];
    __shared__ float wsm[CH * NCELL];

    const int t = blockIdx.y;
    const int c0 = blockIdx.x * CH;
    const int tid = threadIdx.x;

    {
        const float4* gw4 = (const float4*)(g_tapw + t * NCELL * 16);
        const int4*   gi4 = (const int4*)(g_tapi + t * NCELL * 16);
        for (int i = tid; i < NCELL * 4; i += 256) {
            ((float4*)s_tw)[i] = gw4[i];
            ((int4*)s_ti)[i] = gi4[i];
        }
    }
    const float4* src4 = (const float4*)x_t;
    for (int i = tid; i < CH * 49; i += 256) {
        int c = i / 49, q = i - (i / 49) * 49;
        float4 v = src4[(size_t)((c0 + c) * TT + t) * 49 + q];
        float* dst = ts + c * TSTR + q * 4;
        dst[0] = v.x; dst[1] = v.y; dst[2] = v.z; dst[3] = v.w;
    }
    for (int i = tid; i < CH * NCELL; i += 256) {
        int p = i / NCELL, cell = i - (i / NCELL) * NCELL;
        gsm[p * NCELL + cell] = g_G[(size_t)(c0 + p) * NCOLS + t * NCELL + cell];
    }
    __syncthreads();

    // Phase 2: gather. warp = one cell x 32 channels; stride 197 coprime 32.
    for (int j = tid; j < NCELL * 32; j += 256) {
        int cell = j >> 5;
        int p = j & 31;
        const float* tp = ts + p * TSTR;
        const float4* tw4 = (const float4*)(s_tw + cell * 16);
        const int4*   ti4 = (const int4*)(s_ti + cell * 16);
        float mr = 0.0f;
#pragma unroll
        for (int g4 = 0; g4 < 4; g4++) {
            float4 w = tw4[g4];
            int4 ix = ti4[g4];
            mr = fmaf(w.x, tp[ix.x], mr);
            mr = fmaf(w.y, tp[ix.y], mr);
            mr = fmaf(w.z, tp[ix.z], mr);
            mr = fmaf(w.w, tp[ix.w], mr);
        }
        wsm[p * NCELL + cell] = gsm[p * NCELL + cell] * mr;
    }
    __syncthreads();

    // Phase 3: scatter weighted values into tiles (bijective placement).
    {
        const int mt = g_win[t * 2 + 0];
        const int ml = g_win[t * 2 + 1];
        for (int j = tid; j < NCELL * 32; j += 256) {
            int cell = j >> 5;
            int p = j & 31;
            int oy = cell / NOUT;
            int ox = cell - oy * NOUT;
            int pix = (mt + oy) * WF + (ml + ox);
            ts[p * TSTR + pix] += wsm[p * NCELL + cell];
        }
    }
    __syncthreads();

    // Phase 4: branch-free copy smem -> gmem
    float4* dst4 = (float4*)out;
    for (int i = tid; i < CH * 49; i += 256) {
        int c = i / 49, q = i - (i / 49) * 49;
        const float* tp = ts + c * TSTR + q * 4;
        dst4[(size_t)((c0 + c) * TT + t) * 49 + q] =
            make_float4(tp[0], tp[1], tp[2], tp[3]);
    }
}

// ---------------------------------------------------------------------------
// Launch
// ---------------------------------------------------------------------------
extern "C" void kernel_launch(void* const* d_in, const int* in_sizes, int n_in,
                              void* d_out, int out_size) {
    const float* y      = (const float*)d_in[0];
    const float* x_t    = (const float*)d_in[1];
    const float* rois   = (const float*)d_in[2];
    const float* conv_w = (const float*)d_in[3];
    const float* conv_b = (const float*)d_in[4];
    const float* gamma  = (const float*)d_in[5];
    const float* beta   = (const float*)d_in[6];
    const float* rmean  = (const float*)d_in[7];
    const float* rvar   = (const float*)d_in[8];
    float* out = (float*)d_out;

    prep_kernel<<<W8BLK + PK2BLK + TT, 256>>>(conv_w, y, rois);
    {
        cudaFuncSetAttribute(gemm_bn_gelu_kernel,
                             cudaFuncAttributeMaxDynamicSharedMemorySize, SMEM_BYTES);
        dim3 grid(NPAD / BN, COUT / BM);  // (13, 48) = 624 CTAs
        gemm_bn_gelu_kernel<<<grid, 128, SMEM_BYTES>>>(conv_b, gamma, beta, rmean, rvar);
    }
    {
        dim3 grid(COUT / CH, TT);
        roi_place_kernel<<<grid, 256>>>(x_t, out);
    }
}

// round 14
// speedup vs baseline: 1.5396x; 1.0025x over previous
#include <cuda_runtime.h>
#include <cuda_fp16.h>
#include <math.h>
#include <stdint.h>

// Problem constants
#define CIN   1536
#define COUT  3072
#define TT    16
#define HF    14
#define WF    14
#define NOUT  7
#define NCELL (NOUT * NOUT)        // 49
#define NCOLS (TT * NCELL)         // 784
#define NPAD  832                  // 13 * 64
#define PLANE (HF * WF)            // 196

// ---------------------------------------------------------------------------
// Device scratch
// ---------------------------------------------------------------------------
__device__ __align__(16) __half g_Wh[COUT * CIN];           // W fp16
__device__ __align__(16) __half g_Bh[CIN * NPAD];           // y fp16, k-major
__device__ __align__(16) float g_G[COUT * NCOLS];           // gelu(bn(conv))
__device__ __align__(16) float g_tapw[TT * NCELL * 16];
__device__ __align__(16) int   g_tapi[TT * NCELL * 16];
__device__ int   g_win[TT * 2];

// ---------------------------------------------------------------------------
// Kernel P: merged convert_w (4x float4/thread) + pack (4 elems/thread) + taps
// ---------------------------------------------------------------------------
#define W16CNT ((COUT * CIN) / 16)               // 294912
#define W16BLK ((W16CNT + 255) / 256)            // 1152
#define PK4CNT ((CIN * NPAD) / 4)                // 319488
#define PK4BLK ((PK4CNT + 255) / 256)            // 1248

__global__ void prep_kernel(const float* __restrict__ W, const float* __restrict__ y,
                            const float* __restrict__ rois) {
    if (blockIdx.x < W16BLK) {
        int i = blockIdx.x * 256 + threadIdx.x;
        if (i >= W16CNT) return;
        float4 v0 = ((const float4*)W)[i * 4 + 0];
        float4 v1 = ((const float4*)W)[i * 4 + 1];
        float4 v2 = ((const float4*)W)[i * 4 + 2];
        float4 v3 = ((const float4*)W)[i * 4 + 3];
        __half2* Wh2 = (__half2*)g_Wh;
        Wh2[i * 8 + 0] = __half2{__float2half_rn(v0.x), __float2half_rn(v0.y)};
        Wh2[i * 8 + 1] = __half2{__float2half_rn(v0.z), __float2half_rn(v0.w)};
        Wh2[i * 8 + 2] = __half2{__float2half_rn(v1.x), __float2half_rn(v1.y)};
        Wh2[i * 8 + 3] = __half2{__float2half_rn(v1.z), __float2half_rn(v1.w)};
        Wh2[i * 8 + 4] = __half2{__float2half_rn(v2.x), __float2half_rn(v2.y)};
        Wh2[i * 8 + 5] = __half2{__float2half_rn(v2.z), __float2half_rn(v2.w)};
        Wh2[i * 8 + 6] = __half2{__float2half_rn(v3.x), __float2half_rn(v3.y)};
        Wh2[i * 8 + 7] = __half2{__float2half_rn(v3.z), __float2half_rn(v3.w)};
    } else if (blockIdx.x < W16BLK + PK4BLK) {
        int i4 = (blockIdx.x - W16BLK) * 256 + threadIdx.x;
        if (i4 >= PK4CNT) return;
        int idx = i4 * 4;                 // NPAD % 4 == 0 -> same k row
        int k = idx / NPAD;
        int n0 = idx - k * NPAD;
        float v[4] = {0.0f, 0.0f, 0.0f, 0.0f};
#pragma unroll
        for (int j = 0; j < 4; j++) {
            int n = n0 + j;
            if (n < NCOLS) {
                int t = n / NCELL;
                int r = n - t * NCELL;
                int oy = r / NOUT;
                int ox = r - oy * NOUT;
                v[j] = y[((k * TT + t) * HF + 2 * oy) * WF + 2 * ox];
            }
        }
        __half2* Bh2 = (__half2*)g_Bh;
        Bh2[i4 * 2 + 0] = __half2{__float2half_rn(v[0]), __float2half_rn(v[1])};
        Bh2[i4 * 2 + 1] = __half2{__float2half_rn(v[2]), __float2half_rn(v[3])};
    } else {
        const int t = blockIdx.x - (W16BLK + PK4BLK);
        const int cell = threadIdx.x;
        if (cell >= NCELL) return;
        const float SC = 1.0f / 16.0f;
        float bx1 = rois[t * 4 + 0] * SC;
        float by1 = rois[t * 4 + 1] * SC;
        float bx2 = rois[t * 4 + 2] * SC;
        float by2 = rois[t * 4 + 3] * SC;
        float bw = fmaxf(bx2 - bx1, 1.0f) / (float)NOUT;
        float bh = fmaxf(by2 - by1, 1.0f) / (float)NOUT;

        if (cell == 0) {
            int sxi = (int)floorf(bx1);
            int syi = (int)floorf(by1);
            int exi = (int)ceilf(bx2);
            int eyi = (int)ceilf(by2);
            g_win[t * 2 + 0] = (syi + NOUT < HF) ? syi : (eyi - NOUT);
            g_win[t * 2 + 1] = (sxi + NOUT < HF) ? sxi : (exi - NOUT);
        }

        int oy = cell / NOUT;
        int ox = cell - oy * NOUT;
        float* tw = g_tapw + (t * NCELL + cell) * 16;
        int*   ti = g_tapi + (t * NCELL + cell) * 16;

#pragma unroll
        for (int s = 0; s < 2; s++) {
#pragma unroll
            for (int r = 0; r < 2; r++) {
                int base = (s * 2 + r) * 4;
                float py = by1 + ((float)oy + ((float)s + 0.5f) * 0.5f) * bh;
                float px = bx1 + ((float)ox + ((float)r + 0.5f) * 0.5f) * bw;
                bool oob = (py < -1.0f) | (py > (float)HF) | (px < -1.0f) | (px > (float)WF);
                if (oob) {
                    tw[base + 0] = 0.f; tw[base + 1] = 0.f; tw[base + 2] = 0.f; tw[base + 3] = 0.f;
                    ti[base + 0] = 0;   ti[base + 1] = 0;   ti[base + 2] = 0;   ti[base + 3] = 0;
                } else {
                    float yc = fminf(fmaxf(py, 0.0f), (float)(HF - 1));
                    float xc = fminf(fmaxf(px, 0.0f), (float)(WF - 1));
                    int y0 = (int)floorf(yc);
                    int x0 = (int)floorf(xc);
                    int y1i = min(y0 + 1, HF - 1);
                    int x1i = min(x0 + 1, WF - 1);
                    float ly = yc - (float)y0;
                    float lx = xc - (float)x0;
                    tw[base + 0] = 0.25f * (1.f - ly) * (1.f - lx);
                    tw[base + 1] = 0.25f * (1.f - ly) * lx;
                    tw[base + 2] = 0.25f * ly * (1.f - lx);
                    tw[base + 3] = 0.25f * ly * lx;
                    ti[base + 0] = y0 * WF + x0;
                    ti[base + 1] = y0 * WF + x1i;
                    ti[base + 2] = y1i * WF + x0;
                    ti[base + 3] = y1i * WF + x1i;
                }
            }
        }
    }
}

// ---------------------------------------------------------------------------
// Kernel 2: fp16 tensor-core GEMM + bias + BN + exact GELU
// BM=64, BN=64, BK=32; 128 threads; 4-stage cp.async depth-3.
// Fragment loads hoisted: 8 ldsm up front, then 32 back-to-back MMAs.
// ---------------------------------------------------------------------------
#define BM 64
#define BN 64
#define BK 32
#define KSTEPS (CIN / BK)     // 48
#define ASTR 40
#define BSTR 72

#define AH_OFF 0
#define BH_OFF (BM * ASTR)                  // 2560
#define STAGE_ELEMS (BH_OFF + BK * BSTR)    // 4864 halfs = 9728B
#define NSTAGE 4
#define SMEM_BYTES (NSTAGE * STAGE_ELEMS * 2)  // 38912

__device__ __forceinline__ void cp16(void* smem, const void* gmem) {
    unsigned sa = (unsigned)__cvta_generic_to_shared(smem);
    asm volatile("cp.async.cg.shared.global [%0], [%1], 16;\n" :: "r"(sa), "l"(gmem));
}
__device__ __forceinline__ void ldsm4(unsigned* r, const void* p) {
    unsigned a = (unsigned)__cvta_generic_to_shared(p);
    asm volatile("ldmatrix.sync.aligned.m8n8.x4.shared.b16 {%0,%1,%2,%3}, [%4];\n"
        : "=r"(r[0]), "=r"(r[1]), "=r"(r[2]), "=r"(r[3]) : "r"(a));
}
__device__ __forceinline__ void ldsm4t(unsigned* r, const void* p) {
    unsigned a = (unsigned)__cvta_generic_to_shared(p);
    asm volatile("ldmatrix.sync.aligned.m8n8.x4.trans.shared.b16 {%0,%1,%2,%3}, [%4];\n"
        : "=r"(r[0]), "=r"(r[1]), "=r"(r[2]), "=r"(r[3]) : "r"(a));
}

#define MMA_F16(c, a, b0, b1)                                               \
    asm volatile(                                                           \
        "mma.sync.aligned.m16n8k16.row.col.f32.f16.f16.f32 "                \
        "{%0,%1,%2,%3}, {%4,%5,%6,%7}, {%8,%9}, {%0,%1,%2,%3};\n"           \
        : "+f"(c[0]), "+f"(c[1]), "+f"(c[2]), "+f"(c[3])                    \
        : "r"(a[0]), "r"(a[1]), "r"(a[2]), "r"(a[3]), "r"(b0), "r"(b1))

extern __shared__ __half smem_buf[];

__global__ void __launch_bounds__(128) gemm_bn_gelu_kernel(
    const float* __restrict__ bias,
    const float* __restrict__ gamma,
    const float* __restrict__ beta,
    const float* __restrict__ rmean,
    const float* __restrict__ rvar)
{
    const int tid = threadIdx.x;
    const int bm = blockIdx.y * BM;
    const int bn = blockIdx.x * BN;

    const int lane = tid & 31;
    const int warp = tid >> 5;
    const int wm = warp >> 1;
    const int wn = warp & 1;
    const int frow = lane >> 2;
    const int fcolp = (lane & 3) * 2;
    const int sel = lane >> 3;
    const int lr = lane & 7;

    float acc[2][4][4];
#pragma unroll
    for (int mt = 0; mt < 2; mt++)
#pragma unroll
        for (int nt = 0; nt < 4; nt++)
#pragma unroll
            for (int i = 0; i < 4; i++) acc[mt][nt][i] = 0.0f;

    auto prefetch = [&](int s, int k0) {
        __half* st = smem_buf + s * STAGE_ELEMS;
#pragma unroll
        for (int c = tid; c < 256; c += 128) {
            int row = c >> 2;
            int u = c & 3;
            cp16(&st[AH_OFF + row * ASTR + u * 8],
                 &g_Wh[(size_t)(bm + row) * CIN + k0 + u * 8]);
        }
#pragma unroll
        for (int c = tid; c < 256; c += 128) {
            int row = c >> 3;
            int u = c & 7;
            cp16(&st[BH_OFF + row * BSTR + u * 8],
                 &g_Bh[(size_t)(k0 + row) * NPAD + bn + u * 8]);
        }
        asm volatile("cp.async.commit_group;\n");
    };

    auto consume = [&](int s) {
        const __half* st = smem_buf + s * STAGE_ELEMS;
        const unsigned short* sAh = (const unsigned short*)(st + AH_OFF);
        const unsigned short* sBh = (const unsigned short*)(st + BH_OFF);
        // Hoist ALL fragment loads (both k-halves) before any MMA.
        unsigned ah[2][2][4], bh[2][2][4];   // [h][mt|np][4]
        const int arow = (sel & 1) * 8 + lr;
        const int akof = (sel >> 1) * 8;
#pragma unroll
        for (int h = 0; h < 2; h++) {
            const int kb = h * 16;
#pragma unroll
            for (int mt = 0; mt < 2; mt++) {
                int r = wm * 32 + mt * 16 + arow;
                ldsm4(ah[h][mt], &sAh[r * ASTR + kb + akof]);
            }
#pragma unroll
            for (int np = 0; np < 2; np++) {
                int kr = kb + (sel & 1) * 8 + lr;
                int nc = wn * 32 + np * 16 + (sel >> 1) * 8;
                ldsm4t(bh[h][np], &sBh[kr * BSTR + nc]);
            }
        }
#pragma unroll
        for (int h = 0; h < 2; h++)
#pragma unroll
            for (int np = 0; np < 2; np++)
#pragma unroll
                for (int q = 0; q < 2; q++) {
                    int nt = np * 2 + q;
#pragma unroll
                    for (int mt = 0; mt < 2; mt++)
                        MMA_F16(acc[mt][nt], ah[h][mt],
                                bh[h][np][q * 2], bh[h][np][q * 2 + 1]);
                }
    };

    prefetch(0, 0);
    prefetch(1, BK);
    prefetch(2, 2 * BK);

    for (int ks = 0; ks < KSTEPS; ks++) {
        int rem = KSTEPS - 1 - ks;
        if (rem >= 2)      asm volatile("cp.async.wait_group 2;\n");
        else if (rem == 1) asm volatile("cp.async.wait_group 1;\n");
        else               asm volatile("cp.async.wait_group 0;\n");
        __syncthreads();
        if (ks + 3 < KSTEPS) prefetch((ks + 3) & 3, (ks + 3) * BK);
        consume(ks & 3);
    }

    // Epilogue: bias + BN + exact GELU -> g_G
#pragma unroll
    for (int mt = 0; mt < 2; mt++) {
        int r0g = bm + wm * 32 + mt * 16 + frow;
#pragma unroll
        for (int half = 0; half < 2; half++) {
            int o = r0g + half * 8;
            float inv = gamma[o] * rsqrtf(rvar[o] + 1e-6f);
            float b0 = bias[o];
            float mu = rmean[o];
            float be = beta[o];
#pragma unroll
            for (int nt = 0; nt < 4; nt++) {
                int n = bn + wn * 32 + nt * 8 + fcolp;
                if (n < NCOLS) {
                    float v0 = acc[mt][nt][half * 2 + 0] + b0;
                    float v1 = acc[mt][nt][half * 2 + 1] + b0;
                    v0 = (v0 - mu) * inv + be;
                    v1 = (v1 - mu) * inv + be;
                    v0 = v0 * normcdff(v0);
                    v1 = v1 * normcdff(v1);
                    *(float2*)&g_G[(size_t)o * NCOLS + n] = make_float2(v0, v1);
                }
            }
        }
    }
}

// ---------------------------------------------------------------------------
// Kernel 3: ROI-align + place + residual (v5, unchanged from R13)
// ---------------------------------------------------------------------------
#define CH 32
#define TSTR 197

__global__ void __launch_bounds__(256) roi_place_kernel(
    const float* __restrict__ x_t,
    float* __restrict__ out)
{
    __shared__ __align__(16) float s_tw[NCELL * 16];
    __shared__ __align__(16) int   s_ti[NCELL * 16];
    __shared__ float ts[CH * TSTR];
    __shared__ float gsm[CH * NCELL];
    __shared__ float wsm[CH * NCELL];

    const int t = blockIdx.y;
    const int c0 = blockIdx.x * CH;
    const int tid = threadIdx.x;

    {
        const float4* gw4 = (const float4*)(g_tapw + t * NCELL * 16);
        const int4*   gi4 = (const int4*)(g_tapi + t * NCELL * 16);
        for (int i = tid; i < NCELL * 4; i += 256) {
            ((float4*)s_tw)[i] = gw4[i];
            ((int4*)s_ti)[i] = gi4[i];
        }
    }
    const float4* src4 = (const float4*)x_t;
    for (int i = tid; i < CH * 49; i += 256) {
        int c = i / 49, q = i - (i / 49) * 49;
        float4 v = src4[(size_t)((c0 + c) * TT + t) * 49 + q];
        float* dst = ts + c * TSTR + q * 4;
        dst[0] = v.x; dst[1] = v.y; dst[2] = v.z; dst[3] = v.w;
    }
    for (int i = tid; i < CH * NCELL; i += 256) {
        int p = i / NCELL, cell = i - (i / NCELL) * NCELL;
        gsm[p * NCELL + cell] = g_G[(size_t)(c0 + p) * NCOLS + t * NCELL + cell];
    }
    __syncthreads();

    for (int j = tid; j < NCELL * 32; j += 256) {
        int cell = j >> 5;
        int p = j & 31;
        const float* tp = ts + p * TSTR;
        const float4* tw4 = (const float4*)(s_tw + cell * 16);
        const int4*   ti4 = (const int4*)(s_ti + cell * 16);
        float mr = 0.0f;
#pragma unroll
        for (int g4 = 0; g4 < 4; g4++) {
            float4 w = tw4[g4];
            int4 ix = ti4[g4];
            mr = fmaf(w.x, tp[ix.x], mr);
            mr = fmaf(w.y, tp[ix.y], mr);
            mr = fmaf(w.z, tp[ix.z], mr);
            mr = fmaf(w.w, tp[ix.w], mr);
        }
        wsm[p * NCELL + cell] = gsm[p * NCELL + cell] * mr;
    }
    __syncthreads();

    {
        const int mt = g_win[t * 2 + 0];
        const int ml = g_win[t * 2 + 1];
        for (int j = tid; j < NCELL * 32; j += 256) {
            int cell = j >> 5;
            int p = j & 31;
            int oy = cell / NOUT;
            int ox = cell - oy * NOUT;
            int pix = (mt + oy) * WF + (ml + ox);
            ts[p * TSTR + pix] += wsm[p * NCELL + cell];
        }
    }
    __syncthreads();

    float4* dst4 = (float4*)out;
    for (int i = tid; i < CH * 49; i += 256) {
        int c = i / 49, q = i - (i / 49) * 49;
        const float* tp = ts + c * TSTR + q * 4;
        dst4[(size_t)((c0 + c) * TT + t) * 49 + q] =
            make_float4(tp[0], tp[1], tp[2], tp[3]);
    }
}

// ---------------------------------------------------------------------------
// Launch
// ---------------------------------------------------------------------------
extern "C" void kernel_launch(void* const* d_in, const int* in_sizes, int n_in,
                              void* d_out, int out_size) {
    const float* y      = (const float*)d_in[0];
    const float* x_t    = (const float*)d_in[1];
    const float* rois   = (const float*)d_in[2];
    const float* conv_w = (const float*)d_in[3];
    const float* conv_b = (const float*)d_in[4];
    const float* gamma  = (const float*)d_in[5];
    const float* beta   = (const float*)d_in[6];
    const float* rmean  = (const float*)d_in[7];
    const float* rvar   = (const float*)d_in[8];
    float* out = (float*)d_out;

    prep_kernel<<<W16BLK + PK4BLK + TT, 256>>>(conv_w, y, rois);
    {
        cudaFuncSetAttribute(gemm_bn_gelu_kernel,
                             cudaFuncAttributeMaxDynamicSharedMemorySize, SMEM_BYTES);
        dim3 grid(NPAD / BN, COUT / BM);  // (13, 48) = 624 CTAs
        gemm_bn_gelu_kernel<<<grid, 128, SMEM_BYTES>>>(conv_b, gamma, beta, rmean, rvar);
    }
    {
        dim3 grid(COUT / CH, TT);
        roi_place_kernel<<<grid, 256>>>(x_t, out);
    }
}

// round 15
// speedup vs baseline: 1.5571x; 1.0114x over previous
#include <cuda_runtime.h>
#include <cuda_fp16.h>
#include <math.h>
#include <stdint.h>

// Problem constants
#define CIN   1536
#define COUT  3072
#define TT    16
#define HF    14
#define WF    14
#define NOUT  7
#define NCELL (NOUT * NOUT)        // 49
#define NCOLS (TT * NCELL)         // 784
#define NPAD  832                  // 13 * 64
#define PLANE (HF * WF)            // 196

// ---------------------------------------------------------------------------
// Device scratch
// ---------------------------------------------------------------------------
__device__ __align__(16) __half g_Wh[COUT * CIN];           // W fp16
__device__ __align__(16) __half g_Bh[CIN * NPAD];           // y fp16, k-major
__device__ __align__(16) __half g_G[COUT * NCOLS];          // gelu(bn(conv)), fp16
__device__ __align__(16) float g_tapw[TT * NCELL * 16];
__device__ __align__(16) int   g_tapi[TT * NCELL * 16];
__device__ int   g_win[TT * 2];

// ---------------------------------------------------------------------------
// Kernel P: merged convert_w (4x float4/thread) + pack (4 elems/thread) + taps
// ---------------------------------------------------------------------------
#define W16CNT ((COUT * CIN) / 16)
#define W16BLK ((W16CNT + 255) / 256)
#define PK4CNT ((CIN * NPAD) / 4)
#define PK4BLK ((PK4CNT + 255) / 256)

__global__ void prep_kernel(const float* __restrict__ W, const float* __restrict__ y,
                            const float* __restrict__ rois) {
    if (blockIdx.x < W16BLK) {
        int i = blockIdx.x * 256 + threadIdx.x;
        if (i >= W16CNT) return;
        float4 v0 = ((const float4*)W)[i * 4 + 0];
        float4 v1 = ((const float4*)W)[i * 4 + 1];
        float4 v2 = ((const float4*)W)[i * 4 + 2];
        float4 v3 = ((const float4*)W)[i * 4 + 3];
        __half2* Wh2 = (__half2*)g_Wh;
        Wh2[i * 8 + 0] = __half2{__float2half_rn(v0.x), __float2half_rn(v0.y)};
        Wh2[i * 8 + 1] = __half2{__float2half_rn(v0.z), __float2half_rn(v0.w)};
        Wh2[i * 8 + 2] = __half2{__float2half_rn(v1.x), __float2half_rn(v1.y)};
        Wh2[i * 8 + 3] = __half2{__float2half_rn(v1.z), __float2half_rn(v1.w)};
        Wh2[i * 8 + 4] = __half2{__float2half_rn(v2.x), __float2half_rn(v2.y)};
        Wh2[i * 8 + 5] = __half2{__float2half_rn(v2.z), __float2half_rn(v2.w)};
        Wh2[i * 8 + 6] = __half2{__float2half_rn(v3.x), __float2half_rn(v3.y)};
        Wh2[i * 8 + 7] = __half2{__float2half_rn(v3.z), __float2half_rn(v3.w)};
    } else if (blockIdx.x < W16BLK + PK4BLK) {
        int i4 = (blockIdx.x - W16BLK) * 256 + threadIdx.x;
        if (i4 >= PK4CNT) return;
        int idx = i4 * 4;
        int k = idx / NPAD;
        int n0 = idx - k * NPAD;
        float v[4] = {0.0f, 0.0f, 0.0f, 0.0f};
#pragma unroll
        for (int j = 0; j < 4; j++) {
            int n = n0 + j;
            if (n < NCOLS) {
                int t = n / NCELL;
                int r = n - t * NCELL;
                int oy = r / NOUT;
                int ox = r - oy * NOUT;
                v[j] = y[((k * TT + t) * HF + 2 * oy) * WF + 2 * ox];
            }
        }
        __half2* Bh2 = (__half2*)g_Bh;
        Bh2[i4 * 2 + 0] = __half2{__float2half_rn(v[0]), __float2half_rn(v[1])};
        Bh2[i4 * 2 + 1] = __half2{__float2half_rn(v[2]), __float2half_rn(v[3])};
    } else {
        const int t = blockIdx.x - (W16BLK + PK4BLK);
        const int cell = threadIdx.x;
        if (cell >= NCELL) return;
        const float SC = 1.0f / 16.0f;
        float bx1 = rois[t * 4 + 0] * SC;
        float by1 = rois[t * 4 + 1] * SC;
        float bx2 = rois[t * 4 + 2] * SC;
        float by2 = rois[t * 4 + 3] * SC;
        float bw = fmaxf(bx2 - bx1, 1.0f) / (float)NOUT;
        float bh = fmaxf(by2 - by1, 1.0f) / (float)NOUT;

        if (cell == 0) {
            int sxi = (int)floorf(bx1);
            int syi = (int)floorf(by1);
            int exi = (int)ceilf(bx2);
            int eyi = (int)ceilf(by2);
            g_win[t * 2 + 0] = (syi + NOUT < HF) ? syi : (eyi - NOUT);
            g_win[t * 2 + 1] = (sxi + NOUT < HF) ? sxi : (exi - NOUT);
        }

        int oy = cell / NOUT;
        int ox = cell - oy * NOUT;
        float* tw = g_tapw + (t * NCELL + cell) * 16;
        int*   ti = g_tapi + (t * NCELL + cell) * 16;

#pragma unroll
        for (int s = 0; s < 2; s++) {
#pragma unroll
            for (int r = 0; r < 2; r++) {
                int base = (s * 2 + r) * 4;
                float py = by1 + ((float)oy + ((float)s + 0.5f) * 0.5f) * bh;
                float px = bx1 + ((float)ox + ((float)r + 0.5f) * 0.5f) * bw;
                bool oob = (py < -1.0f) | (py > (float)HF) | (px < -1.0f) | (px > (float)WF);
                if (oob) {
                    tw[base + 0] = 0.f; tw[base + 1] = 0.f; tw[base + 2] = 0.f; tw[base + 3] = 0.f;
                    ti[base + 0] = 0;   ti[base + 1] = 0;   ti[base + 2] = 0;   ti[base + 3] = 0;
                } else {
                    float yc = fminf(fmaxf(py, 0.0f), (float)(HF - 1));
                    float xc = fminf(fmaxf(px, 0.0f), (float)(WF - 1));
                    int y0 = (int)floorf(yc);
                    int x0 = (int)floorf(xc);
                    int y1i = min(y0 + 1, HF - 1);
                    int x1i = min(x0 + 1, WF - 1);
                    float ly = yc - (float)y0;
                    float lx = xc - (float)x0;
                    tw[base + 0] = 0.25f * (1.f - ly) * (1.f - lx);
                    tw[base + 1] = 0.25f * (1.f - ly) * lx;
                    tw[base + 2] = 0.25f * ly * (1.f - lx);
                    tw[base + 3] = 0.25f * ly * lx;
                    ti[base + 0] = y0 * WF + x0;
                    ti[base + 1] = y0 * WF + x1i;
                    ti[base + 2] = y1i * WF + x0;
                    ti[base + 3] = y1i * WF + x1i;
                }
            }
        }
    }
}

// ---------------------------------------------------------------------------
// Kernel 2: fp16 tensor-core GEMM + bias + BN + exact GELU (fp16 g_G output)
// BM=64, BN=64, BK=32; 128 threads; 4-stage cp.async depth-3.
// ---------------------------------------------------------------------------
#define BM 64
#define BN 64
#define BK 32
#define KSTEPS (CIN / BK)     // 48
#define ASTR 40
#define BSTR 72

#define AH_OFF 0
#define BH_OFF (BM * ASTR)                  // 2560
#define STAGE_ELEMS (BH_OFF + BK * BSTR)    // 4864 halfs = 9728B
#define NSTAGE 4
#define SMEM_BYTES (NSTAGE * STAGE_ELEMS * 2)  // 38912

__device__ __forceinline__ void cp16(void* smem, const void* gmem) {
    unsigned sa = (unsigned)__cvta_generic_to_shared(smem);
    asm volatile("cp.async.cg.shared.global [%0], [%1], 16;\n" :: "r"(sa), "l"(gmem));
}
__device__ __forceinline__ void ldsm4(unsigned* r, const void* p) {
    unsigned a = (unsigned)__cvta_generic_to_shared(p);
    asm volatile("ldmatrix.sync.aligned.m8n8.x4.shared.b16 {%0,%1,%2,%3}, [%4];\n"
        : "=r"(r[0]), "=r"(r[1]), "=r"(r[2]), "=r"(r[3]) : "r"(a));
}
__device__ __forceinline__ void ldsm4t(unsigned* r, const void* p) {
    unsigned a = (unsigned)__cvta_generic_to_shared(p);
    asm volatile("ldmatrix.sync.aligned.m8n8.x4.trans.shared.b16 {%0,%1,%2,%3}, [%4];\n"
        : "=r"(r[0]), "=r"(r[1]), "=r"(r[2]), "=r"(r[3]) : "r"(a));
}

#define MMA_F16(c, a, b0, b1)                                               \
    asm volatile(                                                           \
        "mma.sync.aligned.m16n8k16.row.col.f32.f16.f16.f32 "                \
        "{%0,%1,%2,%3}, {%4,%5,%6,%7}, {%8,%9}, {%0,%1,%2,%3};\n"           \
        : "+f"(c[0]), "+f"(c[1]), "+f"(c[2]), "+f"(c[3])                    \
        : "r"(a[0]), "r"(a[1]), "r"(a[2]), "r"(a[3]), "r"(b0), "r"(b1))

extern __shared__ __half smem_buf[];

__global__ void __launch_bounds__(128) gemm_bn_gelu_kernel(
    const float* __restrict__ bias,
    const float* __restrict__ gamma,
    const float* __restrict__ beta,
    const float* __restrict__ rmean,
    const float* __restrict__ rvar)
{
    const int tid = threadIdx.x;
    const int bm = blockIdx.y * BM;
    const int bn = blockIdx.x * BN;

    const int lane = tid & 31;
    const int warp = tid >> 5;
    const int wm = warp >> 1;
    const int wn = warp & 1;
    const int frow = lane >> 2;
    const int fcolp = (lane & 3) * 2;
    const int sel = lane >> 3;
    const int lr = lane & 7;

    float acc[2][4][4];
#pragma unroll
    for (int mt = 0; mt < 2; mt++)
#pragma unroll
        for (int nt = 0; nt < 4; nt++)
#pragma unroll
            for (int i = 0; i < 4; i++) acc[mt][nt][i] = 0.0f;

    auto prefetch = [&](int s, int k0) {
        __half* st = smem_buf + s * STAGE_ELEMS;
#pragma unroll
        for (int c = tid; c < 256; c += 128) {
            int row = c >> 2;
            int u = c & 3;
            cp16(&st[AH_OFF + row * ASTR + u * 8],
                 &g_Wh[(size_t)(bm + row) * CIN + k0 + u * 8]);
        }
#pragma unroll
        for (int c = tid; c < 256; c += 128) {
            int row = c >> 3;
            int u = c & 7;
            cp16(&st[BH_OFF + row * BSTR + u * 8],
                 &g_Bh[(size_t)(k0 + row) * NPAD + bn + u * 8]);
        }
        asm volatile("cp.async.commit_group;\n");
    };

    auto consume = [&](int s) {
        const __half* st = smem_buf + s * STAGE_ELEMS;
        const unsigned short* sAh = (const unsigned short*)(st + AH_OFF);
        const unsigned short* sBh = (const unsigned short*)(st + BH_OFF);
#pragma unroll
        for (int h = 0; h < 2; h++) {
            const int kb = h * 16;
            unsigned ah[2][4], bh[2][4];
            const int arow = (sel & 1) * 8 + lr;
            const int akof = (sel >> 1) * 8;
#pragma unroll
            for (int mt = 0; mt < 2; mt++) {
                int r = wm * 32 + mt * 16 + arow;
                ldsm4(ah[mt], &sAh[r * ASTR + kb + akof]);
            }
#pragma unroll
            for (int np = 0; np < 2; np++) {
                int kr = kb + (sel & 1) * 8 + lr;
                int nc = wn * 32 + np * 16 + (sel >> 1) * 8;
                ldsm4t(bh[np], &sBh[kr * BSTR + nc]);
            }
#pragma unroll
            for (int np = 0; np < 2; np++)
#pragma unroll
                for (int q = 0; q < 2; q++) {
                    int nt = np * 2 + q;
#pragma unroll
                    for (int mt = 0; mt < 2; mt++)
                        MMA_F16(acc[mt][nt], ah[mt], bh[np][q * 2], bh[np][q * 2 + 1]);
                }
        }
    };

    prefetch(0, 0);
    prefetch(1, BK);
    prefetch(2, 2 * BK);

    for (int ks = 0; ks < KSTEPS; ks++) {
        int rem = KSTEPS - 1 - ks;
        if (rem >= 2)      asm volatile("cp.async.wait_group 2;\n");
        else if (rem == 1) asm volatile("cp.async.wait_group 1;\n");
        else               asm volatile("cp.async.wait_group 0;\n");
        __syncthreads();
        if (ks + 3 < KSTEPS) prefetch((ks + 3) & 3, (ks + 3) * BK);
        consume(ks & 3);
    }

    // Epilogue: bias + BN + exact GELU -> g_G (fp16)
#pragma unroll
    for (int mt = 0; mt < 2; mt++) {
        int r0g = bm + wm * 32 + mt * 16 + frow;
#pragma unroll
        for (int half = 0; half < 2; half++) {
            int o = r0g + half * 8;
            float inv = gamma[o] * rsqrtf(rvar[o] + 1e-6f);
            float b0 = bias[o];
            float mu = rmean[o];
            float be = beta[o];
#pragma unroll
            for (int nt = 0; nt < 4; nt++) {
                int n = bn + wn * 32 + nt * 8 + fcolp;
                if (n < NCOLS) {
                    float v0 = acc[mt][nt][half * 2 + 0] + b0;
                    float v1 = acc[mt][nt][half * 2 + 1] + b0;
                    v0 = (v0 - mu) * inv + be;
                    v1 = (v1 - mu) * inv + be;
                    v0 = v0 * normcdff(v0);
                    v1 = v1 * normcdff(v1);
                    *(__half2*)&g_G[(size_t)o * NCOLS + n] =
                        __half2{__float2half_rn(v0), __float2half_rn(v1)};
                }
            }
        }
    }
}

// ---------------------------------------------------------------------------
// Kernel 3: ROI-align + place + residual (v5 + fp16 gsm -> 7 CTAs/SM)
// ---------------------------------------------------------------------------
#define CH 32
#define TSTR 197

__global__ void __launch_bounds__(256) roi_place_kernel(
    const float* __restrict__ x_t,
    float* __restrict__ out)
{
    __shared__ __align__(16) float s_tw[NCELL * 16];
    __shared__ __align__(16) int   s_ti[NCELL * 16];
    __shared__ float ts[CH * TSTR];
    __shared__ __align__(4) __half gsm[CH * NCELL];
    __shared__ float wsm[CH * NCELL];

    const int t = blockIdx.y;
    const int c0 = blockIdx.x * CH;
    const int tid = threadIdx.x;

    {
        const float4* gw4 = (const float4*)(g_tapw + t * NCELL * 16);
        const int4*   gi4 = (const int4*)(g_tapi + t * NCELL * 16);
        for (int i = tid; i < NCELL * 4; i += 256) {
            ((float4*)s_tw)[i] = gw4[i];
            ((int4*)s_ti)[i] = gi4[i];
        }
    }
    const float4* src4 = (const float4*)x_t;
    for (int i = tid; i < CH * 49; i += 256) {
        int c = i / 49, q = i - (i / 49) * 49;
        float4 v = src4[(size_t)((c0 + c) * TT + t) * 49 + q];
        float* dst = ts + c * TSTR + q * 4;
        dst[0] = v.x; dst[1] = v.y; dst[2] = v.z; dst[3] = v.w;
    }
    for (int i = tid; i < CH * NCELL; i += 256) {
        int p = i / NCELL, cell = i - (i / NCELL) * NCELL;
        gsm[p * NCELL + cell] = g_G[(size_t)(c0 + p) * NCOLS + t * NCELL + cell];
    }
    __syncthreads();

    for (int j = tid; j < NCELL * 32; j += 256) {
        int cell = j >> 5;
        int p = j & 31;
        const float* tp = ts + p * TSTR;
        const float4* tw4 = (const float4*)(s_tw + cell * 16);
        const int4*   ti4 = (const int4*)(s_ti + cell * 16);
        float mr = 0.0f;
#pragma unroll
        for (int g4 = 0; g4 < 4; g4++) {
            float4 w = tw4[g4];
            int4 ix = ti4[g4];
            mr = fmaf(w.x, tp[ix.x], mr);
            mr = fmaf(w.y, tp[ix.y], mr);
            mr = fmaf(w.z, tp[ix.z], mr);
            mr = fmaf(w.w, tp[ix.w], mr);
        }
        wsm[p * NCELL + cell] = __half2float(gsm[p * NCELL + cell]) * mr;
    }
    __syncthreads();

    {
        const int mt = g_win[t * 2 + 0];
        const int ml = g_win[t * 2 + 1];
        for (int j = tid; j < NCELL * 32; j += 256) {
            int cell = j >> 5;
            int p = j & 31;
            int oy = cell / NOUT;
            int ox = cell - oy * NOUT;
            int pix = (mt + oy) * WF + (ml + ox);
            ts[p * TSTR + pix] += wsm[p * NCELL + cell];
        }
    }
    __syncthreads();

    float4* dst4 = (float4*)out;
    for (int i = tid; i < CH * 49; i += 256) {
        int c = i / 49, q = i - (i / 49) * 49;
        const float* tp = ts + c * TSTR + q * 4;
        dst4[(size_t)((c0 + c) * TT + t) * 49 + q] =
            make_float4(tp[0], tp[1], tp[2], tp[3]);
    }
}

// ---------------------------------------------------------------------------
// Launch
// ---------------------------------------------------------------------------
extern "C" void kernel_launch(void* const* d_in, const int* in_sizes, int n_in,
                              void* d_out, int out_size) {
    const float* y      = (const float*)d_in[0];
    const float* x_t    = (const float*)d_in[1];
    const float* rois   = (const float*)d_in[2];
    const float* conv_w = (const float*)d_in[3];
    const float* conv_b = (const float*)d_in[4];
    const float* gamma  = (const float*)d_in[5];
    const float* beta   = (const float*)d_in[6];
    const float* rmean  = (const float*)d_in[7];
    const float* rvar   = (const float*)d_in[8];
    float* out = (float*)d_out;

    prep_kernel<<<W16BLK + PK4BLK + TT, 256>>>(conv_w, y, rois);
    {
        cudaFuncSetAttribute(gemm_bn_gelu_kernel,
                             cudaFuncAttributeMaxDynamicSharedMemorySize, SMEM_BYTES);
        dim3 grid(NPAD / BN, COUT / BM);  // (13, 48) = 624 CTAs
        gemm_bn_gelu_kernel<<<grid, 128, SMEM_BYTES>>>(conv_b, gamma, beta, rmean, rvar);
    }
    {
        dim3 grid(COUT / CH, TT);
        roi_place_kernel<<<grid, 256>>>(x_t, out);
    }
}